// round 10
// baseline (speedup 1.0000x reference)
#include <cuda_runtime.h>
#include <math.h>

// pyGAMNet on GB300.
// Cols 0..47: per-feature scalar MLP 1->40->20->1 (ReLU)  == scalar function f_n(x).
// Cols 48..63: class_bias[c, (int)x] gather.
//
// R10: y-sample tables (513 fp32 per feature) instead of (m,c) pairs -> smem
// ~100.5KB per block -> TWO 1024-thread blocks per SM (64 warps, 2x latency
// hiding). Chord reconstructed on the fly: r = fma((y1-y0)*invw, x-xL, y0).
// Uniform branch-free path for numeric + categorical quads.

#define BSZ   131072
#define NCOL  64
#define NF    48
#define H0N   40
#define H1N   20

#define NB    512
#define NPTS  513
#define XMIN  (-6.0f)
#define XMAX  (6.0f)
#define WB    (12.0f / 512.0f)        // 3/128, exact in fp32
#define SCALE (512.0f / 12.0f)
#define INVW  (512.0f / 12.0f)

#define EVAL_TPB   1024
#define EVAL_GRID  296                // 2 blocks per SM
#define ROWS_PB    ((BSZ + EVAL_GRID - 1) / EVAL_GRID)   // 443

// smem floats: 12 numeric regions [f][p] (4*513, stride padded to 2053 ==5 mod 32
// so the 16 q-lane base banks 5q mod 32 are all distinct), then 4 cat regions.
#define REGY       2053                       // 4*513 + 1
#define CATREG     133                        // 4*33 + 1
#define CATOFF     (12 * REGY)                // 24636
#define TAB_F      (CATOFF + 4 * CATREG)      // 25168
#define SMEM_EVAL  (TAB_F * 4)                // 100672 B per block

__device__ float g_ytab[NF][NPTS];    // exact MLP samples at grid points

// ---------------------------------------------------------------------------
// Exact fallback: full MLP eval for one (feature, x). ~Never executed.
// ---------------------------------------------------------------------------
__device__ __noinline__ float mlp_exact(
    int n, float x,
    const float* __restrict__ W0, const float* __restrict__ b0,
    const float* __restrict__ W1, const float* __restrict__ b1,
    const float* __restrict__ W2, const float* __restrict__ b2)
{
    float acc[H1N];
    for (int k = 0; k < H1N; k++) acc[k] = b1[n * H1N + k];
    for (int j = 0; j < H0N; j++) {
        const float h0 = fmaxf(fmaf(x, W0[n * H0N + j], b0[n * H0N + j]), 0.0f);
        const float* w1r = &W1[(n * H0N + j) * H1N];
        for (int k = 0; k < H1N; k++) acc[k] = fmaf(w1r[k], h0, acc[k]);
    }
    float o = b2[n];
    for (int k = 0; k < H1N; k++) o = fmaf(fmaxf(acc[k], 0.0f), W2[n * H1N + k], o);
    return o;
}

// ---------------------------------------------------------------------------
// Precompute: grid (48, 2). Block (n, chunk) samples 257 grid points.
// Chunk boundary point written by both chunks (same value, benign).
// ---------------------------------------------------------------------------
__global__ __launch_bounds__(256) void gam_precompute_kernel(
    const float* __restrict__ W0, const float* __restrict__ b0,
    const float* __restrict__ W1, const float* __restrict__ b1,
    const float* __restrict__ W2, const float* __restrict__ b2)
{
    __shared__ float sw0[H0N], sb0[H0N];
    __shared__ float sW1[H0N * H1N];
    __shared__ float sb1[H1N], sw2[H1N];
    __shared__ float sb2;

    const int n  = blockIdx.x;
    const int p0 = blockIdx.y * 256;
    const int t  = threadIdx.x;

    for (int i = t; i < H0N * H1N; i += 256) sW1[i] = W1[n * H0N * H1N + i];
    if (t < H0N) {
        sw0[t] = W0[n * H0N + t];
        sb0[t] = b0[n * H0N + t];
    }
    if (t >= 64 && t < 64 + H1N) sb1[t - 64] = b1[n * H1N + (t - 64)];
    if (t >= 96 && t < 96 + H1N) sw2[t - 96] = W2[n * H1N + (t - 96)];
    if (t == 128) sb2 = b2[n];
    __syncthreads();

    for (int i = t; i < 257; i += 256) {
        const int p = p0 + i;
        if (p >= NPTS) break;
        const float x = fmaf((float)p, WB, XMIN);   // exact grid point
        float acc[H1N];
        #pragma unroll
        for (int k = 0; k < H1N; k++) acc[k] = sb1[k];
        #pragma unroll 4
        for (int j = 0; j < H0N; j++) {
            const float h0 = fmaxf(fmaf(x, sw0[j], sb0[j]), 0.0f);
            const float* w1r = &sW1[j * H1N];
            #pragma unroll
            for (int k = 0; k < H1N; k++) acc[k] = fmaf(w1r[k], h0, acc[k]);
        }
        float o = sb2;
        #pragma unroll
        for (int k = 0; k < H1N; k++) o = fmaf(fmaxf(acc[k], 0.0f), sw2[k], o);
        g_ytab[n][p] = o;
    }
}

// ---------------------------------------------------------------------------
// Eval: 296 blocks x 1024 threads (2 blocks/SM, 64 warps).
// Thread -> (row-lane = tid/16, quad q = tid%16): handles cols 4q..4q+3.
// smem float index: q*REGY + f*NPTS + p   (cat: CATOFF + cq*CATREG + f*33 + p)
// ---------------------------------------------------------------------------
struct QCtx {
    const float* qbase;
    float scale, off, bound, xmin, wb, invw;
    int nbm1, fstride, q;
};

__device__ __forceinline__ void eval_quad(
    const QCtx& ctx, const float4 v, float4& o,
    const float* __restrict__ W0, const float* __restrict__ b0,
    const float* __restrict__ W1, const float* __restrict__ b1,
    const float* __restrict__ W2, const float* __restrict__ b2)
{
    const float xs[4] = {v.x, v.y, v.z, v.w};
    float os[4];
    bool bad = false;
    #pragma unroll
    for (int f = 0; f < 4; f++) {
        const float x = xs[f];
        int b = (int)fmaf(x, ctx.scale, ctx.off);
        b = max(min(b, ctx.nbm1), 0);
        const float* base = ctx.qbase + f * ctx.fstride;
        const float y0 = base[b];
        const float y1 = base[b + 1];
        const float m  = (y1 - y0) * ctx.invw;
        const float xL = fmaf((float)b, ctx.wb, ctx.xmin);
        os[f] = fmaf(m, x - xL, y0);
        bad |= (fabsf(x) > ctx.bound);
    }
    if (__builtin_expect(bad, 0)) {   // numeric |x|>6: ~never
        #pragma unroll
        for (int f = 0; f < 4; f++)
            if (fabsf(xs[f]) > ctx.bound)
                os[f] = mlp_exact(ctx.q * 4 + f, xs[f], W0, b0, W1, b1, W2, b2);
    }
    o = make_float4(os[0], os[1], os[2], os[3]);
}

__global__ __launch_bounds__(EVAL_TPB, 2) void gam_eval_kernel(
    const float* __restrict__ in,
    const float* __restrict__ cb,
    const float* __restrict__ W0, const float* __restrict__ b0,
    const float* __restrict__ W1, const float* __restrict__ b1,
    const float* __restrict__ W2, const float* __restrict__ b2,
    float* __restrict__ out)
{
    extern __shared__ float sY[];

    const int tid = threadIdx.x;

    // numeric tables: g_ytab[n][p] -> sY[(n>>2)*REGY + (n&3)*NPTS + p]
    for (int i = tid; i < NF * NPTS; i += EVAL_TPB) {
        const int n = i / NPTS;
        const int p = i - n * NPTS;
        sY[(n >> 2) * REGY + (n & 3) * NPTS + p] = g_ytab[n][p];
    }
    // cat tables: 33 entries per cat feature (y[32] = y[31] pad)
    for (int i = tid; i < 16 * 33; i += EVAL_TPB) {
        const int c = i / 33;
        const int p = i - c * 33;
        sY[CATOFF + (c >> 2) * CATREG + (c & 3) * 33 + min(p, 31) + (p - min(p, 31))]
            = cb[c * 32 + min(p, 31)];
    }
    __syncthreads();

    const int start = blockIdx.x * ROWS_PB;
    const int rend  = min(start + ROWS_PB, BSZ);

    const int q    = tid & 15;
    const int rrel = tid >> 4;
    const bool isnum = (q < 12);

    QCtx ctx;
    ctx.q       = q;
    ctx.qbase   = isnum ? (sY + q * REGY)
                        : (sY + CATOFF + (q - 12) * CATREG);
    ctx.scale   = isnum ? SCALE : 1.0f;
    ctx.off     = isnum ? 256.0f : 0.0f;     // 6 * 512/12 = 256 exact
    ctx.bound   = isnum ? XMAX : 1e30f;
    ctx.xmin    = isnum ? XMIN : 0.0f;
    ctx.wb      = isnum ? WB : 1.0f;
    ctx.invw    = isnum ? INVW : 1.0f;
    ctx.nbm1    = isnum ? (NB - 1) : 31;
    ctx.fstride = isnum ? NPTS : 33;

    const int colq = q * 4;

    int r0 = start;
    for (; r0 + 128 <= rend; r0 += 128) {
        const int row0 = r0 + rrel;
        const float4 v0 = __ldcs(reinterpret_cast<const float4*>(in + (row0     ) * NCOL + colq));
        const float4 v1 = __ldcs(reinterpret_cast<const float4*>(in + (row0 + 64) * NCOL + colq));
        float4 o;
        eval_quad(ctx, v0, o, W0, b0, W1, b1, W2, b2);
        __stcs(reinterpret_cast<float4*>(out + (row0     ) * NCOL + colq), o);
        eval_quad(ctx, v1, o, W0, b0, W1, b1, W2, b2);
        __stcs(reinterpret_cast<float4*>(out + (row0 + 64) * NCOL + colq), o);
    }
    for (; r0 < rend; r0 += 64) {
        const int row = r0 + rrel;
        if (row < rend) {
            const float4 v = __ldcs(reinterpret_cast<const float4*>(in + row * NCOL + colq));
            float4 o;
            eval_quad(ctx, v, o, W0, b0, W1, b1, W2, b2);
            __stcs(reinterpret_cast<float4*>(out + row * NCOL + colq), o);
        }
    }
}

extern "C" void kernel_launch(void* const* d_in, const int* in_sizes, int n_in,
                              void* d_out, int out_size)
{
    const float* in = (const float*)d_in[0];
    const float* W0 = (const float*)d_in[1];
    const float* b0 = (const float*)d_in[2];
    const float* W1 = (const float*)d_in[3];
    const float* b1 = (const float*)d_in[4];
    const float* W2 = (const float*)d_in[5];
    const float* b2 = (const float*)d_in[6];
    const float* cb = (const float*)d_in[7];
    float* out = (float*)d_out;

    static bool attr_done = false;
    if (!attr_done) {
        cudaFuncSetAttribute(gam_eval_kernel,
                             cudaFuncAttributeMaxDynamicSharedMemorySize,
                             (int)SMEM_EVAL);
        attr_done = true;
    }

    dim3 pgrid(NF, 3, 1);   // chunks at p0 = 0, 256, 512 (3rd covers tail point)
    gam_precompute_kernel<<<dim3(NF, 2, 1), 256>>>(W0, b0, W1, b1, W2, b2);

    gam_eval_kernel<<<EVAL_GRID, EVAL_TPB, SMEM_EVAL>>>(
        in, cb, W0, b0, W1, b1, W2, b2, out);
}

// round 11
// speedup vs baseline: 1.1634x; 1.1634x over previous
#include <cuda_runtime.h>
#include <math.h>

// pyGAMNet on GB300.
// Cols 0..47: per-feature scalar MLP 1->40->20->1 (ReLU)  == scalar function f_n(x).
// Cols 48..63: class_bias[c, (int)x] gather.
//
// R11: R8's proven eval body (one LDS.64 (m,c) gather + fma per element, uniform
// branch-free numeric/cat path) but with NB=384 tables split across TWO block
// types (A: cols 0..31, B: cols 32..63). Uniform ~96KB smem -> 2 blocks/SM ->
// 64 warps/SM at unchanged wavefronts-per-element.

#define BSZ   131072
#define NCOL  64
#define NF    48
#define H0N   40
#define H1N   20

#define NB    384
#define NPTS  385
#define XMIN  (-6.0f)
#define XMAX  (6.0f)
#define WB    (12.0f / 384.0f)        // 1/32, exact in fp32
#define SCALE 32.0f
#define OFFB  192.0f                  // 6*32, exact
#define INVW  32.0f

#define EVAL_TPB   1024
#define NSLOT      148
#define EVAL_GRID  (2 * NSLOT)        // 296: A = bid<148, B = bid-148
#define ROWS_PB    ((BSZ + NSLOT - 1) / NSLOT)   // 886

// smem float2 regions: stride 1537 (=384*4+1). A: 8 numeric regions.
// B: 4 numeric regions + 4 cat regions (129 float2 each) at CATOFF.
#define REG_F2     1537
#define CAT_F2     129
#define CATOFF_F2  (4 * REG_F2)                  // 6148
#define TAB_F2     (8 * REG_F2)                  // 12296
#define SMEM_EVAL  (TAB_F2 * 8)                  // 98368 B

__device__ float2 g_tab[NF][NB];      // per bucket: (slope m, intercept c)

// ---------------------------------------------------------------------------
// Exact fallback: full MLP eval for one (feature, x). ~Never executed.
// ---------------------------------------------------------------------------
__device__ __noinline__ float mlp_exact(
    int n, float x,
    const float* __restrict__ W0, const float* __restrict__ b0,
    const float* __restrict__ W1, const float* __restrict__ b1,
    const float* __restrict__ W2, const float* __restrict__ b2)
{
    float acc[H1N];
    for (int k = 0; k < H1N; k++) acc[k] = b1[n * H1N + k];
    for (int j = 0; j < H0N; j++) {
        const float h0 = fmaxf(fmaf(x, W0[n * H0N + j], b0[n * H0N + j]), 0.0f);
        const float* w1r = &W1[(n * H0N + j) * H1N];
        for (int k = 0; k < H1N; k++) acc[k] = fmaf(w1r[k], h0, acc[k]);
    }
    float o = b2[n];
    for (int k = 0; k < H1N; k++) o = fmaf(fmaxf(acc[k], 0.0f), W2[n * H1N + k], o);
    return o;
}

// ---------------------------------------------------------------------------
// Precompute: grid (48, 2). Block (n, chunk) samples 193 grid points and emits
// 192 buckets as (m, c): f(x) ~ m*x + c on the bucket.
// ---------------------------------------------------------------------------
__global__ __launch_bounds__(256) void gam_precompute_kernel(
    const float* __restrict__ W0, const float* __restrict__ b0,
    const float* __restrict__ W1, const float* __restrict__ b1,
    const float* __restrict__ W2, const float* __restrict__ b2)
{
    __shared__ float sw0[H0N], sb0[H0N];
    __shared__ float sW1[H0N * H1N];
    __shared__ float sb1[H1N], sw2[H1N];
    __shared__ float sb2;
    __shared__ float yv[193];

    const int n  = blockIdx.x;
    const int p0 = blockIdx.y * 192;
    const int t  = threadIdx.x;

    for (int i = t; i < H0N * H1N; i += 256) sW1[i] = W1[n * H0N * H1N + i];
    if (t < H0N) {
        sw0[t] = W0[n * H0N + t];
        sb0[t] = b0[n * H0N + t];
    }
    if (t >= 64 && t < 64 + H1N) sb1[t - 64] = b1[n * H1N + (t - 64)];
    if (t >= 96 && t < 96 + H1N) sw2[t - 96] = W2[n * H1N + (t - 96)];
    if (t == 128) sb2 = b2[n];
    __syncthreads();

    if (t < 193) {
        const float x = fmaf((float)(p0 + t), WB, XMIN);   // exact grid point
        float acc[H1N];
        #pragma unroll
        for (int k = 0; k < H1N; k++) acc[k] = sb1[k];
        #pragma unroll 4
        for (int j = 0; j < H0N; j++) {
            const float h0 = fmaxf(fmaf(x, sw0[j], sb0[j]), 0.0f);
            const float* w1r = &sW1[j * H1N];
            #pragma unroll
            for (int k = 0; k < H1N; k++) acc[k] = fmaf(w1r[k], h0, acc[k]);
        }
        float o = sb2;
        #pragma unroll
        for (int k = 0; k < H1N; k++) o = fmaf(fmaxf(acc[k], 0.0f), sw2[k], o);
        yv[t] = o;
    }
    __syncthreads();

    if (t < 192) {
        const int b = p0 + t;
        const float m  = (yv[t + 1] - yv[t]) * INVW;
        const float xL = fmaf((float)b, WB, XMIN);
        const float c  = fmaf(-m, xL, yv[t]);
        g_tab[n][b] = make_float2(m, c);
    }
}

// ---------------------------------------------------------------------------
// Eval: 296 blocks x 1024 threads (2 blocks/SM, 64 warps).
// Type A (bid<148): cols 0..31.  Type B: cols 32..63 (16 numeric + 16 cat).
// Thread -> (row-lane = tid/8, quad q = tid%8): handles cols colbase..+3.
// Gather: one LDS.64 (m,c) at qbase[b*4+f]; r = fma(m, x, c).
// ---------------------------------------------------------------------------
struct QCtx {
    const float2* qbase;
    float scale, off, bound;
    int nbm1, nfb;
};

__device__ __forceinline__ void eval_quad(
    const QCtx& ctx, const float4 v, float4& o,
    const float* __restrict__ W0, const float* __restrict__ b0,
    const float* __restrict__ W1, const float* __restrict__ b1,
    const float* __restrict__ W2, const float* __restrict__ b2)
{
    const float xs[4] = {v.x, v.y, v.z, v.w};
    float os[4];
    bool bad = false;
    #pragma unroll
    for (int f = 0; f < 4; f++) {
        const float x = xs[f];
        int b = (int)fmaf(x, ctx.scale, ctx.off);
        b = min(max(b, 0), ctx.nbm1);
        const float2 mc = ctx.qbase[b * 4 + f];
        os[f] = fmaf(mc.x, x, mc.y);
        bad |= (fabsf(x) > ctx.bound);
    }
    if (__builtin_expect(bad, 0)) {   // numeric |x|>6: ~never
        #pragma unroll
        for (int f = 0; f < 4; f++)
            if (fabsf(xs[f]) > ctx.bound)
                os[f] = mlp_exact(ctx.nfb + f, xs[f], W0, b0, W1, b1, W2, b2);
    }
    o = make_float4(os[0], os[1], os[2], os[3]);
}

__global__ __launch_bounds__(EVAL_TPB, 2) void gam_eval_kernel(
    const float* __restrict__ in,
    const float* __restrict__ cb,
    const float* __restrict__ W0, const float* __restrict__ b0,
    const float* __restrict__ W1, const float* __restrict__ b1,
    const float* __restrict__ W2, const float* __restrict__ b2,
    float* __restrict__ out)
{
    extern __shared__ float2 sTab[];

    const int bid   = blockIdx.x;
    const bool typeA = (bid < NSLOT);
    const int slot  = typeA ? bid : bid - NSLOT;
    const int tid   = threadIdx.x;

    // ---- stage this block's tables ----
    if (typeA) {
        // features 0..31 -> regions 0..7
        for (int i = tid; i < 32 * NB; i += EVAL_TPB) {
            const int n = i / NB;
            const int b = i - n * NB;
            sTab[(n >> 2) * REG_F2 + b * 4 + (n & 3)] = g_tab[n][b];
        }
    } else {
        // features 32..47 -> regions 0..3
        for (int i = tid; i < 16 * NB; i += EVAL_TPB) {
            const int n32 = i / NB;
            const int b   = i - n32 * NB;
            sTab[(n32 >> 2) * REG_F2 + b * 4 + (n32 & 3)] = g_tab[32 + n32][b];
        }
        // cat features 0..15 -> cat regions 0..3 (m=0, c=bias)
        for (int i = tid; i < 16 * 32; i += EVAL_TPB) {
            const int c = i >> 5;
            const int x = i & 31;
            sTab[CATOFF_F2 + (c >> 2) * CAT_F2 + x * 4 + (c & 3)] =
                make_float2(0.0f, cb[i]);
        }
    }
    __syncthreads();

    const int q    = tid & 7;
    const int rrel = tid >> 3;          // 0..127
    const int colbase = (typeA ? 0 : 32) + q * 4;
    const bool isnum  = typeA || (q < 4);

    QCtx ctx;
    ctx.qbase = typeA ? (sTab + q * REG_F2)
                      : (isnum ? (sTab + q * REG_F2)
                               : (sTab + CATOFF_F2 + (q - 4) * CAT_F2));
    ctx.scale = isnum ? SCALE : 1.0f;
    ctx.off   = isnum ? OFFB  : 0.0f;
    ctx.bound = isnum ? XMAX  : 1e30f;
    ctx.nbm1  = isnum ? (NB - 1) : 31;
    ctx.nfb   = colbase;                // numeric feature base (cols==features)

    const int start = slot * ROWS_PB;
    const int rend  = min(start + ROWS_PB, BSZ);

    int r0 = start;
    for (; r0 + 256 <= rend; r0 += 256) {
        const int rowa = r0 + rrel;
        const int rowb = rowa + 128;
        const float4 va = *reinterpret_cast<const float4*>(in + rowa * NCOL + colbase);
        const float4 vb = *reinterpret_cast<const float4*>(in + rowb * NCOL + colbase);
        float4 o;
        eval_quad(ctx, va, o, W0, b0, W1, b1, W2, b2);
        *reinterpret_cast<float4*>(out + rowa * NCOL + colbase) = o;
        eval_quad(ctx, vb, o, W0, b0, W1, b1, W2, b2);
        *reinterpret_cast<float4*>(out + rowb * NCOL + colbase) = o;
    }
    for (; r0 < rend; r0 += 128) {
        const int row = r0 + rrel;
        if (row < rend) {
            const float4 v = *reinterpret_cast<const float4*>(in + row * NCOL + colbase);
            float4 o;
            eval_quad(ctx, v, o, W0, b0, W1, b1, W2, b2);
            *reinterpret_cast<float4*>(out + row * NCOL + colbase) = o;
        }
    }
}

extern "C" void kernel_launch(void* const* d_in, const int* in_sizes, int n_in,
                              void* d_out, int out_size)
{
    const float* in = (const float*)d_in[0];
    const float* W0 = (const float*)d_in[1];
    const float* b0 = (const float*)d_in[2];
    const float* W1 = (const float*)d_in[3];
    const float* b1 = (const float*)d_in[4];
    const float* W2 = (const float*)d_in[5];
    const float* b2 = (const float*)d_in[6];
    const float* cb = (const float*)d_in[7];
    float* out = (float*)d_out;

    static bool attr_done = false;
    if (!attr_done) {
        cudaFuncSetAttribute(gam_eval_kernel,
                             cudaFuncAttributeMaxDynamicSharedMemorySize,
                             (int)SMEM_EVAL);
        attr_done = true;
    }

    gam_precompute_kernel<<<dim3(NF, 2, 1), 256>>>(W0, b0, W1, b1, W2, b2);

    gam_eval_kernel<<<EVAL_GRID, EVAL_TPB, SMEM_EVAL>>>(
        in, cb, W0, b0, W1, b1, W2, b2, out);
}